// round 15
// baseline (speedup 1.0000x reference)
#include <cuda_runtime.h>
#include <cuda_bf16.h>
#include <cstdint>

// Problem constants
#define Bb 8
#define Cc 1024
#define INF 256
#define NH 8
#define OF 128
#define FEAT (NH*OF)          // 1024
#define ROWS (Bb*Cc)          // 8192
#define X_ELEMS (ROWS*FEAT)   // 8388608
#define H_ELE (ROWS*INF)      // 2097152
#define W_ELE (INF*FEAT)      // 262144

// ---------------- device scratch ----
__device__ __nv_bfloat16 g_Whb[ROWS * FEAT];              // bf16 Wh (aggr B operand)
__device__ float g_R [ROWS * FEAT];                       // H@res_W + res_b
__device__ float g_Hout[ROWS * FEAT];                     // x
__device__ float g_es[ROWS * NH];
__device__ float g_ed[ROWS * NH];
__device__ __nv_bfloat16 g_alphaTb[(size_t)Bb * NH * Cc * Cc]; // (b,h,i,j) bf16
// split-bf16 operands for R gemm
__device__ __nv_bfloat16 g_Hh[H_ELE], g_Hl[H_ELE];
__device__ __nv_bfloat16 g_B1h[W_ELE], g_B1l[W_ELE];      // res_W hi/lo
// tf32 operands for Wh gemm
__device__ uint32_t g_Htf[H_ELE];
__device__ uint32_t g_Wtf[W_ELE];

// ---------------- helpers ----
__device__ __forceinline__ void mma_bf16(float4& c, const uint32_t a[4],
                                         uint32_t b0, uint32_t b1) {
    asm volatile(
      "mma.sync.aligned.m16n8k16.row.col.f32.bf16.bf16.f32 "
      "{%0,%1,%2,%3},{%4,%5,%6,%7},{%8,%9},{%0,%1,%2,%3};"
      : "+f"(c.x), "+f"(c.y), "+f"(c.z), "+f"(c.w)
      : "r"(a[0]), "r"(a[1]), "r"(a[2]), "r"(a[3]), "r"(b0), "r"(b1));
}
__device__ __forceinline__ void mma_tf32(float4& c, const uint32_t a[4],
                                         uint32_t b0, uint32_t b1) {
    asm volatile(
      "mma.sync.aligned.m16n8k8.row.col.f32.tf32.tf32.f32 "
      "{%0,%1,%2,%3},{%4,%5,%6,%7},{%8,%9},{%0,%1,%2,%3};"
      : "+f"(c.x), "+f"(c.y), "+f"(c.z), "+f"(c.w)
      : "r"(a[0]), "r"(a[1]), "r"(a[2]), "r"(a[3]), "r"(b0), "r"(b1));
}
__device__ __forceinline__ uint32_t f2tf32(float x) {
    uint32_t r;
    asm("cvt.rna.tf32.f32 %0, %1;" : "=r"(r) : "f"(x));
    return r;
}
__device__ __forceinline__ uint32_t packbf(float x, float y) {
    __nv_bfloat162 t;
    t.x = __float2bfloat16(x); t.y = __float2bfloat16(y);
    return *reinterpret_cast<uint32_t*>(&t);
}
#define CP16(dst, src) \
    asm volatile("cp.async.cg.shared.global [%0], [%1], 16;" :: "r"(dst), "l"(src))
#define CP_COMMIT() asm volatile("cp.async.commit_group;")
#define CP_WAIT(N)  asm volatile("cp.async.wait_group %0;" :: "n"(N))
#define LDSM_X4(r, addr) \
    asm volatile("ldmatrix.sync.aligned.m8n8.x4.shared.b16 {%0,%1,%2,%3}, [%4];" \
      : "=r"((r)[0]), "=r"((r)[1]), "=r"((r)[2]), "=r"((r)[3]) : "r"(addr))
#define LDSM_X4T(r, addr) \
    asm volatile("ldmatrix.sync.aligned.m8n8.x4.trans.shared.b16 {%0,%1,%2,%3}, [%4];" \
      : "=r"((r)[0]), "=r"((r)[1]), "=r"((r)[2]), "=r"((r)[3]) : "r"(addr))

// =======================================================================
// K0: prep — H: bf16 hi/lo + tf32;  W: tf32;  res_W: bf16 hi/lo.
// =======================================================================
__global__ __launch_bounds__(256) void prep_kernel(
    const float* __restrict__ H, const float* __restrict__ W,
    const float* __restrict__ rW)
{
    const int idx = blockIdx.x * 256 + threadIdx.x;
    const int nH = H_ELE / 4, nW = W_ELE / 4;
    if (idx < nH) {
        float4 v = reinterpret_cast<const float4*>(H)[idx];
        float hx = __bfloat162float(__float2bfloat16(v.x));
        float hy = __bfloat162float(__float2bfloat16(v.y));
        float hz = __bfloat162float(__float2bfloat16(v.z));
        float hw = __bfloat162float(__float2bfloat16(v.w));
        uint2 wh = make_uint2(packbf(v.x, v.y), packbf(v.z, v.w));
        uint2 wl = make_uint2(packbf(v.x - hx, v.y - hy), packbf(v.z - hz, v.w - hw));
        *reinterpret_cast<uint2*>(g_Hh + (size_t)idx * 4) = wh;
        *reinterpret_cast<uint2*>(g_Hl + (size_t)idx * 4) = wl;
        uint4 tf = make_uint4(f2tf32(v.x), f2tf32(v.y), f2tf32(v.z), f2tf32(v.w));
        *reinterpret_cast<uint4*>(g_Htf + (size_t)idx * 4) = tf;
    } else if (idx < nH + nW) {
        int off = idx - nH;
        float4 v = reinterpret_cast<const float4*>(W)[off];
        uint4 tf = make_uint4(f2tf32(v.x), f2tf32(v.y), f2tf32(v.z), f2tf32(v.w));
        *reinterpret_cast<uint4*>(g_Wtf + (size_t)off * 4) = tf;
    } else if (idx < nH + 2 * nW) {
        int off = idx - nH - nW;
        float4 v = reinterpret_cast<const float4*>(rW)[off];
        float hx = __bfloat162float(__float2bfloat16(v.x));
        float hy = __bfloat162float(__float2bfloat16(v.y));
        float hz = __bfloat162float(__float2bfloat16(v.z));
        float hw = __bfloat162float(__float2bfloat16(v.w));
        uint2 wh = make_uint2(packbf(v.x, v.y), packbf(v.z, v.w));
        uint2 wl = make_uint2(packbf(v.x - hx, v.y - hy), packbf(v.z - hz, v.w - hw));
        *reinterpret_cast<uint2*>(g_B1h + (size_t)off * 4) = wh;
        *reinterpret_cast<uint2*>(g_B1l + (size_t)off * 4) = wl;
    }
}

// =======================================================================
// K1a: Wh GEMM — single-pass TF32. g_Whb = H@W + fused scores.
// =======================================================================
#define PAK 36
#define PBN 136
#define A3 (128 * PAK)
#define B3 (32 * PBN)
#define WH_SMEM (3 * (A3 + B3) * 4)   // 107520 bytes

__global__ __launch_bounds__(256, 2) void wh_gemm(const float* __restrict__ a_attn)
{
    extern __shared__ uint32_t smem_u[];
    const int m0 = blockIdx.y * 128, n0 = blockIdx.x * 128;
    const int hn = blockIdx.x;
    const int tid = threadIdx.x;
    const int wid = tid >> 5, lane = tid & 31;
    const int wm = (wid & 3) * 32, wn = (wid >> 2) * 64;
    const int g = lane >> 2, tg = lane & 3;

    uint32_t sbase = (uint32_t)__cvta_generic_to_shared(smem_u);
    const uint32_t aB = sbase;
    const uint32_t bB = sbase + 3 * A3 * 4;

    float4 acc[2][8];
#pragma unroll
    for (int mt = 0; mt < 2; mt++)
#pragma unroll
        for (int nt = 0; nt < 8; nt++) acc[mt][nt] = make_float4(0.f,0.f,0.f,0.f);

    auto issue = [&](int slot, int k0) {
#pragma unroll
        for (int i = 0; i < 4; i++) {
            int c = tid + i * 256;
            int r = c >> 3, seg = c & 7;
            const uint32_t* src = g_Htf + (size_t)(m0 + r) * INF + k0 + seg * 4;
            uint32_t dst = aB + (slot * A3 + r * PAK + seg * 4) * 4;
            CP16(dst, src);
        }
#pragma unroll
        for (int i = 0; i < 4; i++) {
            int c = tid + i * 256;
            int kr = c >> 5, sg = c & 31;
            const uint32_t* src = g_Wtf + (size_t)(k0 + kr) * FEAT + n0 + sg * 4;
            uint32_t dst = bB + (slot * B3 + kr * PBN + sg * 4) * 4;
            CP16(dst, src);
        }
        CP_COMMIT();
    };

    auto compute = [&](int slot) {
        const uint32_t* As = smem_u + slot * A3;
        const uint32_t* Bs = smem_u + 3 * A3 + slot * B3;
#pragma unroll
        for (int ks = 0; ks < 4; ks++) {
            int kk = ks * 8;
            uint32_t ah[2][4];
#pragma unroll
            for (int mt = 0; mt < 2; mt++) {
                int r = wm + mt * 16 + g;
                ah[mt][0] = As[r       * PAK + kk + tg];
                ah[mt][1] = As[(r + 8) * PAK + kk + tg];
                ah[mt][2] = As[r       * PAK + kk + tg + 4];
                ah[mt][3] = As[(r + 8) * PAK + kk + tg + 4];
            }
#pragma unroll
            for (int nt = 0; nt < 8; nt++) {
                int cx = wn + nt * 8 + g;
                uint32_t b0 = Bs[(kk + tg)     * PBN + cx];
                uint32_t b1 = Bs[(kk + tg + 4) * PBN + cx];
                mma_tf32(acc[0][nt], ah[0], b0, b1);
                mma_tf32(acc[1][nt], ah[1], b0, b1);
            }
        }
    };

    const int NIT = INF / 32;
    issue(0, 0);
    issue(1, 32);
    for (int it = 0; it < NIT; it++) {
        if (it + 2 < NIT) { CP_WAIT(1); } else { CP_WAIT(0); }
        __syncthreads();
        if (it + 2 < NIT) issue((it + 2) % 3, (it + 2) * 32);
        compute(it % 3);
    }

#pragma unroll
    for (int mt = 0; mt < 2; mt++) {
        int r0 = m0 + wm + mt * 16 + g;
#pragma unroll
        for (int nt = 0; nt < 8; nt++) {
            int cc = n0 + wn + nt * 8 + 2 * tg;
            float4 v = acc[mt][nt];
            __nv_bfloat162 q0, q1;
            q0.x = __float2bfloat16(v.x); q0.y = __float2bfloat16(v.y);
            q1.x = __float2bfloat16(v.z); q1.y = __float2bfloat16(v.w);
            *reinterpret_cast<__nv_bfloat162*>(g_Whb + (size_t)r0 * FEAT + cc)       = q0;
            *reinterpret_cast<__nv_bfloat162*>(g_Whb + (size_t)(r0 + 8) * FEAT + cc) = q1;
        }
    }

    {
        float* fs  = reinterpret_cast<float*>(smem_u);
        float* sas = fs;
        float* sad = fs + 128;
        float* sE  = fs + 256;
        float* sD  = fs + 512;
        __syncthreads();
        if (tid < 128)      sas[tid]       = a_attn[hn * 256 + tid];
        else                sad[tid - 128] = a_attn[hn * 256 + 128 + (tid - 128)];
        __syncthreads();

        float ps[2][2] = {{0.f,0.f},{0.f,0.f}};
        float pd[2][2] = {{0.f,0.f},{0.f,0.f}};
#pragma unroll
        for (int mt = 0; mt < 2; mt++)
#pragma unroll
            for (int nt = 0; nt < 8; nt++) {
                int c = wn + nt * 8 + 2 * tg;
                float4 v = acc[mt][nt];
                float a0 = sas[c], a1 = sas[c + 1];
                float d0 = sad[c], d1 = sad[c + 1];
                ps[mt][0] += v.x * a0 + v.y * a1;
                ps[mt][1] += v.z * a0 + v.w * a1;
                pd[mt][0] += v.x * d0 + v.y * d1;
                pd[mt][1] += v.z * d0 + v.w * d1;
            }
#pragma unroll
        for (int mt = 0; mt < 2; mt++)
#pragma unroll
            for (int q = 0; q < 2; q++) {
                ps[mt][q] += __shfl_xor_sync(0xffffffffu, ps[mt][q], 1);
                ps[mt][q] += __shfl_xor_sync(0xffffffffu, ps[mt][q], 2);
                pd[mt][q] += __shfl_xor_sync(0xffffffffu, pd[mt][q], 1);
                pd[mt][q] += __shfl_xor_sync(0xffffffffu, pd[mt][q], 2);
            }
        const int wc = wid >> 2;
        if (tg == 0) {
#pragma unroll
            for (int mt = 0; mt < 2; mt++) {
                int r = wm + mt * 16 + g;
                sE[wc * 128 + r]     = ps[mt][0];
                sE[wc * 128 + r + 8] = ps[mt][1];
                sD[wc * 128 + r]     = pd[mt][0];
                sD[wc * 128 + r + 8] = pd[mt][1];
            }
        }
        __syncthreads();
        if (tid < 128) {
            g_es[(size_t)(m0 + tid) * NH + hn] = sE[tid] + sE[128 + tid];
            g_ed[(size_t)(m0 + tid) * NH + hn] = sD[tid] + sD[128 + tid];
        }
    }
}

// =======================================================================
// K1b: R GEMM — 3-term split-bf16.
// =======================================================================
#define PAS2 20
#define PBN2 68
#define AMAT (128 * PAS2)
#define ASTG (2 * AMAT)
#define BMAT (32 * PBN2)
#define BSTG (2 * BMAT)
#define DG_SMEM (3 * (ASTG + BSTG) * 4)   // 113664 bytes

__global__ __launch_bounds__(256, 2) void r_gemm(const float* __restrict__ res_b)
{
    extern __shared__ uint32_t smem_u[];
    const int m0 = blockIdx.y * 128, n0 = blockIdx.x * 128;
    const int tid = threadIdx.x;
    const int wid = tid >> 5, lane = tid & 31;
    const int wm = (wid & 3) * 32, wn = (wid >> 2) * 64;
    const int g = lane >> 2, tg = lane & 3;

    uint32_t sbase = (uint32_t)__cvta_generic_to_shared(smem_u);
    const uint32_t aB = sbase;
    const uint32_t bB = sbase + 3 * ASTG * 4;

    float4 acc[2][8];
#pragma unroll
    for (int mt = 0; mt < 2; mt++)
#pragma unroll
        for (int nt = 0; nt < 8; nt++) acc[mt][nt] = make_float4(0.f,0.f,0.f,0.f);

    auto issue = [&](int slot, int k0) {
#pragma unroll
        for (int i = 0; i < 2; i++) {
            int c = tid + i * 256;
            int r = c >> 2, seg = c & 3;
            size_t si = (size_t)(m0 + r) * INF + k0 + seg * 8;
            uint32_t d = aB + (slot * ASTG + r * PAS2 + seg * 4) * 4;
            CP16(d, g_Hh + si);
            CP16(d + AMAT * 4, g_Hl + si);
        }
#pragma unroll
        for (int i = 0; i < 2; i++) {
            int c = tid + i * 256;
            int kr = c >> 4, sg = c & 15;
            size_t si = (size_t)(k0 + kr) * FEAT + n0 + sg * 8;
            uint32_t d = bB + (slot * BSTG + kr * PBN2 + sg * 4) * 4;
            CP16(d, g_B1h + si);
            CP16(d + BMAT * 4, g_B1l + si);
        }
        CP_COMMIT();
    };

    auto compute = [&](int slot) {
        const uint32_t aw = aB + slot * ASTG * 4;
        const uint32_t bw = bB + slot * BSTG * 4;
        const int mtx = lane >> 3, mr = lane & 7;
#pragma unroll
        for (int kk2 = 0; kk2 < 2; kk2++) {
            uint32_t ah[2][4], al[2][4];
#pragma unroll
            for (int mt = 0; mt < 2; mt++) {
                int row = wm + mt * 16 + (mtx & 1) * 8 + mr;
                int colw = kk2 * 8 + (mtx >> 1) * 4;
                LDSM_X4(ah[mt], aw + (row * PAS2 + colw) * 4);
                LDSM_X4(al[mt], aw + (AMAT + row * PAS2 + colw) * 4);
            }
#pragma unroll
            for (int p = 0; p < 4; p++) {
                uint32_t bh[4], bl[4];
                int kr = kk2 * 16 + (mtx & 1) * 8 + mr;
                int nb = wn + p * 16 + (mtx >> 1) * 8;
                LDSM_X4T(bh, bw + (kr * PBN2 + (nb >> 1)) * 4);
                LDSM_X4T(bl, bw + (BMAT + kr * PBN2 + (nb >> 1)) * 4);
#pragma unroll
                for (int mt = 0; mt < 2; mt++) {
                    mma_bf16(acc[mt][2*p],   ah[mt], bh[0], bh[1]);
                    mma_bf16(acc[mt][2*p],   ah[mt], bl[0], bl[1]);
                    mma_bf16(acc[mt][2*p],   al[mt], bh[0], bh[1]);
                    mma_bf16(acc[mt][2*p+1], ah[mt], bh[2], bh[3]);
                    mma_bf16(acc[mt][2*p+1], ah[mt], bl[2], bl[3]);
                    mma_bf16(acc[mt][2*p+1], al[mt], bh[2], bh[3]);
                }
            }
        }
    };

    const int NIT = INF / 32;
    issue(0, 0);
    issue(1, 32);
    for (int it = 0; it < NIT; it++) {
        if (it + 2 < NIT) { CP_WAIT(1); } else { CP_WAIT(0); }
        __syncthreads();
        if (it + 2 < NIT) issue((it + 2) % 3, (it + 2) * 32);
        compute(it % 3);
    }

#pragma unroll
    for (int mt = 0; mt < 2; mt++) {
        int r0 = m0 + wm + mt * 16 + g;
#pragma unroll
        for (int nt = 0; nt < 8; nt++) {
            int cc = n0 + wn + nt * 8 + 2 * tg;
            float4 v = acc[mt][nt];
            float bv0 = res_b[cc], bv1 = res_b[cc + 1];
            float2 p0 = make_float2(v.x + bv0, v.y + bv1);
            float2 p1 = make_float2(v.z + bv0, v.w + bv1);
            *reinterpret_cast<float2*>(g_R + (size_t)r0 * FEAT + cc)       = p0;
            *reinterpret_cast<float2*>(g_R + (size_t)(r0 + 8) * FEAT + cc) = p1;
        }
    }
}

// ------------------------------------- K3: softmax (R8 body; bi_base chunking)
__global__ __launch_bounds__(256) void softmax_kernel(
    const float* __restrict__ Amat, float* __restrict__ alpha_out, int bi_base)
{
    __shared__ float s_es[8];
    __shared__ float s_stat[8];
    __shared__ float red[8][8];
    __shared__ float s_redsum[8];
    __shared__ float s_inv;

    const int bi = bi_base + blockIdx.x;
    const int b = bi >> 10, i = bi & 1023;
    const int t = threadIdx.x, wid = t >> 5, lane = t & 31;

    const float* arow = Amat + (size_t)bi * Cc;
    float av[4], psum = 0.f;
#pragma unroll
    for (int jj = 0; jj < 4; jj++) {
        int j = t + jj * 256;
        av[jj] = arow[j];
        psum += av[jj];
    }
#pragma unroll
    for (int o = 16; o; o >>= 1) psum += __shfl_xor_sync(0xffffffffu, psum, o);
    if (!lane) s_redsum[wid] = psum;
    if (t < 8) s_es[t] = g_es[(size_t)bi * NH + t];
    __syncthreads();
    if (t == 0) {
        float s = 0.f;
#pragma unroll
        for (int w = 0; w < 8; w++) s += s_redsum[w];
        s_inv = 1.0f / (s + 1e-8f);
    }
    __syncthreads();

    const float inv = s_inv;
    float es[8];
#pragma unroll
    for (int h = 0; h < 8; h++) es[h] = s_es[h];

    const float CT  = 0.96179669f;      // (1/1.5)*log2(e)
    const float CT5 = 0.19235934f;      // 0.2 * CT
    float vv[4][8];
    float lsum[8];
#pragma unroll
    for (int h = 0; h < 8; h++) lsum[h] = 0.f;

#pragma unroll
    for (int jj = 0; jj < 4; jj++) {
        int j = t + jj * 256;
        const float4* edp = reinterpret_cast<const float4*>(g_ed + ((size_t)b * Cc + j) * NH);
        float4 e0 = edp[0], e1 = edp[1];
        float ed[8] = {e0.x,e0.y,e0.z,e0.w,e1.x,e1.y,e1.z,e1.w};
        float aval = av[jj];
        bool mk = (aval > 0.f) || (j == i);
        float base = fmaf(aval * inv, CT, mk ? 0.f : -9.6179667e8f);
#pragma unroll
        for (int h = 0; h < 8; h++) {
            float s = es[h] + ed[h];
            float c = s > 0.f ? CT : CT5;
            float v = fmaf(s, c, base);
            float ev;
            asm("ex2.approx.f32 %0, %1;" : "=f"(ev) : "f"(v));
            vv[jj][h] = ev;
            lsum[h] += ev;
        }
    }
#pragma unroll
    for (int h = 0; h < 8; h++)
#pragma unroll
        for (int o = 16; o; o >>= 1)
            lsum[h] += __shfl_xor_sync(0xffffffffu, lsum[h], o);
    if (!lane) {
#pragma unroll
        for (int h = 0; h < 8; h++) red[wid][h] = lsum[h];
    }
    __syncthreads();
    if (t < 8) {
        float s = 0.f;
#pragma unroll
        for (int w = 0; w < 8; w++) s += red[w][t];
        s_stat[t] = 1.0f / s;
    }
    __syncthreads();
    float ish[8];
#pragma unroll
    for (int h = 0; h < 8; h++) ish[h] = s_stat[h];

    float* oa = alpha_out + (size_t)bi * (Cc * NH);
#pragma unroll
    for (int jj = 0; jj < 4; jj++) {
        int j = t + jj * 256;
#pragma unroll
        for (int h = 0; h < 8; h++) vv[jj][h] *= ish[h];
        float4 o0 = make_float4(vv[jj][0], vv[jj][1], vv[jj][2], vv[jj][3]);
        float4 o1 = make_float4(vv[jj][4], vv[jj][5], vv[jj][6], vv[jj][7]);
        *reinterpret_cast<float4*>(oa + (size_t)j * NH)     = o0;
        *reinterpret_cast<float4*>(oa + (size_t)j * NH + 4) = o1;
    }
#pragma unroll
    for (int h = 0; h < 8; h++) {
        __nv_bfloat16* ot = g_alphaTb + (((size_t)(b * NH + h)) * Cc + i) * Cc;
#pragma unroll
        for (int jj = 0; jj < 4; jj++) {
            int j = t + jj * 256;
            ot[j] = __float2bfloat16(vv[jj][h]);
        }
    }
}

// =======================================================================
// K4: aggr GEMM (zbase-chunked). per (b,h): Hout = alphaT@Whb + R.
// 128x128 tile, BK=32, 4-stage cp.async + ldmatrix; 2 m-tiles per CTA.
// =======================================================================
#define PAS 20
#define PBS 68
#define A_STG (128 * PAS)
#define B_STG (32 * PBS)
#define NSTAGE 4
#define AGGR_SMEM (NSTAGE * (A_STG + B_STG) * 4)   // 75776 bytes

__global__ __launch_bounds__(256, 2) void aggr_bf16(int zbase)
{
    extern __shared__ uint32_t smem_u[];
    const int z = zbase + blockIdx.z;
    const int b = z >> 3, h = z & 7;
    const __nv_bfloat16* __restrict__ A  = g_alphaTb + (size_t)z * Cc * Cc;
    const __nv_bfloat16* __restrict__ Bp = g_Whb + (size_t)b * Cc * FEAT + h * OF;
    const float* __restrict__ R = g_R    + (size_t)b * Cc * FEAT + h * OF;
    float*       __restrict__ C = g_Hout + (size_t)b * Cc * FEAT + h * OF;

    const int tid = threadIdx.x;
    const int wid = tid >> 5, lane = tid & 31;
    const int wm = (wid & 3) * 32, wn = (wid >> 2) * 64;
    const int g = lane >> 2, tg = lane & 3;

    uint32_t sbase = (uint32_t)__cvta_generic_to_shared(smem_u);
    const uint32_t aBase = sbase;
    const uint32_t bBase = sbase + NSTAGE * A_STG * 4;

    for (int half = 0; half < 2; half++) {
        const int m0 = blockIdx.y * 128 + half * 512;
        if (half) __syncthreads();

        float4 acc[2][8];
#pragma unroll
        for (int mt = 0; mt < 2; mt++)
#pragma unroll
            for (int nt = 0; nt < 8; nt++) acc[mt][nt] = make_float4(0.f,0.f,0.f,0.f);

        auto issue = [&](int slot, int k0) {
#pragma unroll
            for (int i = 0; i < 2; i++) {
                int c = tid + i * 256;
                int r = c >> 2, seg = c & 3;
                const __nv_bfloat16* src = A + (size_t)(m0 + r) * Cc + k0 + seg * 8;
                uint32_t dst = aBase + (slot * A_STG + r * PAS + seg * 4) * 4;
                CP16(dst, src);
            }
#pragma unroll
            for (int i = 0; i < 2; i++) {
                int c = tid + i * 256;
                int kr = c >> 4, seg = c & 15;
                const __nv_bfloat16* src = Bp + (size_t)(k0 + kr) * FEAT + seg * 8;
                uint32_t dst = bBase + (slot * B_STG + kr * PBS + seg * 4) * 4;
                CP16(dst, src);
            }
            CP_COMMIT();
        };

        auto compute = [&](int slot) {
            const uint32_t aw = aBase + slot * A_STG * 4;
            const uint32_t bw = bBase + slot * B_STG * 4;
            const int mtx = lane >> 3;
            const int mr  = lane & 7;
#pragma unroll
            for (int kk2 = 0; kk2 < 2; kk2++) {
                uint32_t af[2][4];
#pragma unroll
                for (int mt = 0; mt < 2; mt++) {
                    int row = wm + mt * 16 + (mtx & 1) * 8 + mr;
                    int col = kk2 * 8 + (mtx >> 1) * 4;
                    LDSM_X4(af[mt], aw + (row * PAS + col) * 4);
                }
#pragma unroll
                for (int p = 0; p < 4; p++) {
                    uint32_t bf[4];
                    int kr = kk2 * 16 + (mtx & 1) * 8 + mr;
                    int nb = wn + p * 16 + (mtx >> 1) * 8;
                    LDSM_X4T(bf, bw + (kr * PBS + (nb >> 1)) * 4);
#pragma unroll
                    for (int mt = 0; mt < 2; mt++) {
                        mma_bf16(acc[mt][2 * p],     af[mt], bf[0], bf[1]);
                        mma_bf16(acc[mt][2 * p + 1], af[mt], bf[2], bf[3]);
                    }
                }
            }
        };

        const int NIT = Cc / 32;
        issue(0, 0);
        issue(1, 32);
        issue(2, 64);
        for (int it = 0; it < NIT; it++) {
            if (it + 3 < NIT)      { CP_WAIT(2); }
            else if (it + 2 < NIT) { CP_WAIT(1); }
            else                   { CP_WAIT(0); }
            __syncthreads();
            if (it + 3 < NIT) issue((it + 3) % NSTAGE, (it + 3) * 32);
            compute(it % NSTAGE);
        }

#pragma unroll
        for (int mt = 0; mt < 2; mt++) {
            int r0 = m0 + wm + mt * 16 + g;
#pragma unroll
            for (int nt = 0; nt < 8; nt++) {
                int cc = wn + nt * 8 + 2 * tg;
                float4 v = acc[mt][nt];
                float2 ra  = *reinterpret_cast<const float2*>(R + (size_t)r0 * FEAT + cc);
                float2 rbv = *reinterpret_cast<const float2*>(R + (size_t)(r0 + 8) * FEAT + cc);
                float2 p0 = make_float2(v.x + ra.x,  v.y + ra.y);
                float2 p1 = make_float2(v.z + rbv.x, v.w + rbv.y);
                *reinterpret_cast<float2*>(C + (size_t)r0 * FEAT + cc)       = p0;
                *reinterpret_cast<float2*>(C + (size_t)(r0 + 8) * FEAT + cc) = p1;
            }
        }
    }
}

// ------------------------------------------------- K5: LayerNorm + ReLU ----
__global__ __launch_bounds__(256) void ln_kernel(
    const float* __restrict__ gamma, const float* __restrict__ beta,
    float* __restrict__ out)
{
    __shared__ float rs[8], rs2[8];
    __shared__ float s_mu, s_rstd;
    const int bi = blockIdx.x;
    const int t = threadIdx.x, wid = t >> 5, lane = t & 31;
    const float* x = g_Hout + (size_t)bi * FEAT;
    float xs[4], s = 0.f, s2 = 0.f;
#pragma unroll
    for (int jj = 0; jj < 4; jj++) {
        float v = x[t + jj * 256];
        xs[jj] = v; s += v; s2 += v * v;
    }
#pragma unroll
    for (int o = 16; o; o >>= 1) {
        s  += __shfl_xor_sync(0xffffffffu, s, o);
        s2 += __shfl_xor_sync(0xffffffffu, s2, o);
    }
    if (!lane) { rs[wid] = s; rs2[wid] = s2; }
    __syncthreads();
    if (t == 0) {
        float ts = 0.f, ts2 = 0.f;
#pragma unroll
        for (int w = 0; w < 8; w++) { ts += rs[w]; ts2 += rs2[w]; }
        float mu = ts * (1.0f / FEAT);
        float var = ts2 * (1.0f / FEAT) - mu * mu;
        s_mu = mu;
        s_rstd = rsqrtf(var + 1e-5f);
    }
    __syncthreads();
    const float mu = s_mu, rstd = s_rstd;
#pragma unroll
    for (int jj = 0; jj < 4; jj++) {
        int f = t + jj * 256;
        float y = (xs[jj] - mu) * rstd * gamma[f] + beta[f];
        out[(size_t)bi * FEAT + f] = fmaxf(y, 0.f);
    }
}

// --------------------------------------------------------------------------
extern "C" void kernel_launch(void* const* d_in, const int* in_sizes, int n_in,
                              void* d_out, int out_size)
{
    const float* H      = (const float*)d_in[0];
    const float* Amat   = (const float*)d_in[1];
    const float* W      = (const float*)d_in[2];
    const float* a_attn = (const float*)d_in[3];
    const float* res_W  = (const float*)d_in[4];
    const float* res_b  = (const float*)d_in[5];
    const float* gamma  = (const float*)d_in[6];
    const float* beta   = (const float*)d_in[7];
    float* out = (float*)d_out;

    static cudaStream_t s2 = nullptr;
    static cudaEvent_t evP, evS0, evS1, evA;
    static bool inited = false;
    if (!inited) {
        cudaFuncSetAttribute(wh_gemm,
            cudaFuncAttributeMaxDynamicSharedMemorySize, WH_SMEM);
        cudaFuncSetAttribute(r_gemm,
            cudaFuncAttributeMaxDynamicSharedMemorySize, DG_SMEM);
        cudaFuncSetAttribute(aggr_bf16,
            cudaFuncAttributeMaxDynamicSharedMemorySize, AGGR_SMEM);
        cudaStreamCreateWithFlags(&s2, cudaStreamNonBlocking);
        cudaEventCreateWithFlags(&evP,  cudaEventDisableTiming);
        cudaEventCreateWithFlags(&evS0, cudaEventDisableTiming);
        cudaEventCreateWithFlags(&evS1, cudaEventDisableTiming);
        cudaEventCreateWithFlags(&evA,  cudaEventDisableTiming);
        inited = true;
    }

    // K0: prep (main)
    const int prep_tot = (H_ELE + 2 * W_ELE) / 4;
    prep_kernel<<<(prep_tot + 255) / 256, 256>>>(H, W, res_W);
    cudaEventRecord(evP, 0);

    // K1a: Wh gemm (tf32) + fused scores (main)
    dim3 g1(FEAT / 128, ROWS / 128, 1);
    wh_gemm<<<g1, 256, WH_SMEM>>>(a_attn);

    // K1b: R gemm on s2 (after prep) — runs under wh_gemm/softmax
    cudaStreamWaitEvent(s2, evP, 0);
    r_gemm<<<g1, 256, DG_SMEM, s2>>>(res_b);

    // K3: softmax in two batch-halves (main); aggr halves chase on s2
    softmax_kernel<<<ROWS / 2, 256>>>(Amat, out + X_ELEMS, 0);
    cudaEventRecord(evS0, 0);
    softmax_kernel<<<ROWS / 2, 256>>>(Amat, out + X_ELEMS, ROWS / 2);
    cudaEventRecord(evS1, 0);

    // aggr half0 (b 0..3) overlaps softmax half1; r_gemm precedes in s2 order
    cudaStreamWaitEvent(s2, evS0, 0);
    aggr_bf16<<<dim3(1, Cc / 256, 32), 256, AGGR_SMEM, s2>>>(0);
    cudaStreamWaitEvent(s2, evS1, 0);
    aggr_bf16<<<dim3(1, Cc / 256, 32), 256, AGGR_SMEM, s2>>>(32);
    cudaEventRecord(evA, s2);

    // K5: LayerNorm + ReLU (main, after join)
    cudaStreamWaitEvent(0, evA, 0);
    ln_kernel<<<ROWS, 256>>>(gamma, beta, out);
}

// round 16
// speedup vs baseline: 1.1656x; 1.1656x over previous
#include <cuda_runtime.h>
#include <cuda_bf16.h>
#include <cstdint>

// Problem constants
#define Bb 8
#define Cc 1024
#define INF 256
#define NH 8
#define OF 128
#define FEAT (NH*OF)          // 1024
#define ROWS (Bb*Cc)          // 8192
#define X_ELEMS (ROWS*FEAT)   // 8388608
#define H_ELE (ROWS*INF)      // 2097152
#define W_ELE (INF*FEAT)      // 262144

// ---------------- device scratch ----
__device__ __nv_bfloat16 g_Whb[ROWS * FEAT];              // bf16 Wh (aggr B operand)
__device__ float g_R [ROWS * FEAT];                       // H@res_W + res_b
__device__ float g_Hout[ROWS * FEAT];                     // x
__device__ float g_es[ROWS * NH];
__device__ float g_ed[ROWS * NH];
__device__ __nv_bfloat16 g_alphaTb[(size_t)Bb * NH * Cc * Cc]; // (b,h,i,j) bf16
// split-bf16 operands for R gemm
__device__ __nv_bfloat16 g_Hh[H_ELE], g_Hl[H_ELE];
__device__ __nv_bfloat16 g_B1h[W_ELE], g_B1l[W_ELE];      // res_W hi/lo
// tf32 operands for Wh gemm
__device__ uint32_t g_Htf[H_ELE];
__device__ uint32_t g_Wtf[W_ELE];

// ---------------- helpers ----
__device__ __forceinline__ void mma_bf16(float4& c, const uint32_t a[4],
                                         uint32_t b0, uint32_t b1) {
    asm volatile(
      "mma.sync.aligned.m16n8k16.row.col.f32.bf16.bf16.f32 "
      "{%0,%1,%2,%3},{%4,%5,%6,%7},{%8,%9},{%0,%1,%2,%3};"
      : "+f"(c.x), "+f"(c.y), "+f"(c.z), "+f"(c.w)
      : "r"(a[0]), "r"(a[1]), "r"(a[2]), "r"(a[3]), "r"(b0), "r"(b1));
}
__device__ __forceinline__ void mma_tf32(float4& c, const uint32_t a[4],
                                         uint32_t b0, uint32_t b1) {
    asm volatile(
      "mma.sync.aligned.m16n8k8.row.col.f32.tf32.tf32.f32 "
      "{%0,%1,%2,%3},{%4,%5,%6,%7},{%8,%9},{%0,%1,%2,%3};"
      : "+f"(c.x), "+f"(c.y), "+f"(c.z), "+f"(c.w)
      : "r"(a[0]), "r"(a[1]), "r"(a[2]), "r"(a[3]), "r"(b0), "r"(b1));
}
__device__ __forceinline__ uint32_t f2tf32(float x) {
    uint32_t r;
    asm("cvt.rna.tf32.f32 %0, %1;" : "=r"(r) : "f"(x));
    return r;
}
__device__ __forceinline__ uint32_t packbf(float x, float y) {
    __nv_bfloat162 t;
    t.x = __float2bfloat16(x); t.y = __float2bfloat16(y);
    return *reinterpret_cast<uint32_t*>(&t);
}
#define CP16(dst, src) \
    asm volatile("cp.async.cg.shared.global [%0], [%1], 16;" :: "r"(dst), "l"(src))
#define CP_COMMIT() asm volatile("cp.async.commit_group;")
#define CP_WAIT(N)  asm volatile("cp.async.wait_group %0;" :: "n"(N))
#define LDSM_X4(r, addr) \
    asm volatile("ldmatrix.sync.aligned.m8n8.x4.shared.b16 {%0,%1,%2,%3}, [%4];" \
      : "=r"((r)[0]), "=r"((r)[1]), "=r"((r)[2]), "=r"((r)[3]) : "r"(addr))
#define LDSM_X4T(r, addr) \
    asm volatile("ldmatrix.sync.aligned.m8n8.x4.trans.shared.b16 {%0,%1,%2,%3}, [%4];" \
      : "=r"((r)[0]), "=r"((r)[1]), "=r"((r)[2]), "=r"((r)[3]) : "r"(addr))

// =======================================================================
// K0: prep — H: bf16 hi/lo + tf32;  W: tf32;  res_W: bf16 hi/lo.
// =======================================================================
__global__ __launch_bounds__(256) void prep_kernel(
    const float* __restrict__ H, const float* __restrict__ W,
    const float* __restrict__ rW)
{
    const int idx = blockIdx.x * 256 + threadIdx.x;
    const int nH = H_ELE / 4, nW = W_ELE / 4;
    if (idx < nH) {
        float4 v = reinterpret_cast<const float4*>(H)[idx];
        float hx = __bfloat162float(__float2bfloat16(v.x));
        float hy = __bfloat162float(__float2bfloat16(v.y));
        float hz = __bfloat162float(__float2bfloat16(v.z));
        float hw = __bfloat162float(__float2bfloat16(v.w));
        uint2 wh = make_uint2(packbf(v.x, v.y), packbf(v.z, v.w));
        uint2 wl = make_uint2(packbf(v.x - hx, v.y - hy), packbf(v.z - hz, v.w - hw));
        *reinterpret_cast<uint2*>(g_Hh + (size_t)idx * 4) = wh;
        *reinterpret_cast<uint2*>(g_Hl + (size_t)idx * 4) = wl;
        uint4 tf = make_uint4(f2tf32(v.x), f2tf32(v.y), f2tf32(v.z), f2tf32(v.w));
        *reinterpret_cast<uint4*>(g_Htf + (size_t)idx * 4) = tf;
    } else if (idx < nH + nW) {
        int off = idx - nH;
        float4 v = reinterpret_cast<const float4*>(W)[off];
        uint4 tf = make_uint4(f2tf32(v.x), f2tf32(v.y), f2tf32(v.z), f2tf32(v.w));
        *reinterpret_cast<uint4*>(g_Wtf + (size_t)off * 4) = tf;
    } else if (idx < nH + 2 * nW) {
        int off = idx - nH - nW;
        float4 v = reinterpret_cast<const float4*>(rW)[off];
        float hx = __bfloat162float(__float2bfloat16(v.x));
        float hy = __bfloat162float(__float2bfloat16(v.y));
        float hz = __bfloat162float(__float2bfloat16(v.z));
        float hw = __bfloat162float(__float2bfloat16(v.w));
        uint2 wh = make_uint2(packbf(v.x, v.y), packbf(v.z, v.w));
        uint2 wl = make_uint2(packbf(v.x - hx, v.y - hy), packbf(v.z - hz, v.w - hw));
        *reinterpret_cast<uint2*>(g_B1h + (size_t)off * 4) = wh;
        *reinterpret_cast<uint2*>(g_B1l + (size_t)off * 4) = wl;
    }
}

// =======================================================================
// K1a: Wh GEMM — single-pass TF32. g_Whb = H@W + fused scores.
// Grid 8 x 32 = 256 CTAs (one wave @ occ 2); each CTA does TWO m-tiles.
// =======================================================================
#define PAK 36
#define PBN 136
#define A3 (128 * PAK)
#define B3 (32 * PBN)
#define WH_SMEM (3 * (A3 + B3) * 4)   // 107520 bytes

__global__ __launch_bounds__(256, 2) void wh_gemm(const float* __restrict__ a_attn)
{
    extern __shared__ uint32_t smem_u[];
    const int n0 = blockIdx.x * 128;
    const int hn = blockIdx.x;
    const int tid = threadIdx.x;
    const int wid = tid >> 5, lane = tid & 31;
    const int wm = (wid & 3) * 32, wn = (wid >> 2) * 64;
    const int g = lane >> 2, tg = lane & 3;

    uint32_t sbase = (uint32_t)__cvta_generic_to_shared(smem_u);
    const uint32_t aB = sbase;
    const uint32_t bB = sbase + 3 * A3 * 4;

    for (int half = 0; half < 2; half++) {
        const int m0 = blockIdx.y * 128 + half * 4096;
        if (half) __syncthreads();      // protect prior epilogue smem reads

        float4 acc[2][8];
#pragma unroll
        for (int mt = 0; mt < 2; mt++)
#pragma unroll
            for (int nt = 0; nt < 8; nt++) acc[mt][nt] = make_float4(0.f,0.f,0.f,0.f);

        auto issue = [&](int slot, int k0) {
#pragma unroll
            for (int i = 0; i < 4; i++) {
                int c = tid + i * 256;
                int r = c >> 3, seg = c & 7;
                const uint32_t* src = g_Htf + (size_t)(m0 + r) * INF + k0 + seg * 4;
                uint32_t dst = aB + (slot * A3 + r * PAK + seg * 4) * 4;
                CP16(dst, src);
            }
#pragma unroll
            for (int i = 0; i < 4; i++) {
                int c = tid + i * 256;
                int kr = c >> 5, sg = c & 31;
                const uint32_t* src = g_Wtf + (size_t)(k0 + kr) * FEAT + n0 + sg * 4;
                uint32_t dst = bB + (slot * B3 + kr * PBN + sg * 4) * 4;
                CP16(dst, src);
            }
            CP_COMMIT();
        };

        auto compute = [&](int slot) {
            const uint32_t* As = smem_u + slot * A3;
            const uint32_t* Bs = smem_u + 3 * A3 + slot * B3;
#pragma unroll
            for (int ks = 0; ks < 4; ks++) {
                int kk = ks * 8;
                uint32_t ah[2][4];
#pragma unroll
                for (int mt = 0; mt < 2; mt++) {
                    int r = wm + mt * 16 + g;
                    ah[mt][0] = As[r       * PAK + kk + tg];
                    ah[mt][1] = As[(r + 8) * PAK + kk + tg];
                    ah[mt][2] = As[r       * PAK + kk + tg + 4];
                    ah[mt][3] = As[(r + 8) * PAK + kk + tg + 4];
                }
#pragma unroll
                for (int nt = 0; nt < 8; nt++) {
                    int cx = wn + nt * 8 + g;
                    uint32_t b0 = Bs[(kk + tg)     * PBN + cx];
                    uint32_t b1 = Bs[(kk + tg + 4) * PBN + cx];
                    mma_tf32(acc[0][nt], ah[0], b0, b1);
                    mma_tf32(acc[1][nt], ah[1], b0, b1);
                }
            }
        };

        const int NIT = INF / 32;
        issue(0, 0);
        issue(1, 32);
        for (int it = 0; it < NIT; it++) {
            if (it + 2 < NIT) { CP_WAIT(1); } else { CP_WAIT(0); }
            __syncthreads();
            if (it + 2 < NIT) issue((it + 2) % 3, (it + 2) * 32);
            compute(it % 3);
        }

        // epilogue: bf16 Whb
#pragma unroll
        for (int mt = 0; mt < 2; mt++) {
            int r0 = m0 + wm + mt * 16 + g;
#pragma unroll
            for (int nt = 0; nt < 8; nt++) {
                int cc = n0 + wn + nt * 8 + 2 * tg;
                float4 v = acc[mt][nt];
                __nv_bfloat162 q0, q1;
                q0.x = __float2bfloat16(v.x); q0.y = __float2bfloat16(v.y);
                q1.x = __float2bfloat16(v.z); q1.y = __float2bfloat16(v.w);
                *reinterpret_cast<__nv_bfloat162*>(g_Whb + (size_t)r0 * FEAT + cc)       = q0;
                *reinterpret_cast<__nv_bfloat162*>(g_Whb + (size_t)(r0 + 8) * FEAT + cc) = q1;
            }
        }

        // fused e_src / e_dst (smem reuse after mainloop)
        {
            float* fs  = reinterpret_cast<float*>(smem_u);
            float* sas = fs;
            float* sad = fs + 128;
            float* sE  = fs + 256;
            float* sD  = fs + 512;
            __syncthreads();
            if (tid < 128)      sas[tid]       = a_attn[hn * 256 + tid];
            else                sad[tid - 128] = a_attn[hn * 256 + 128 + (tid - 128)];
            __syncthreads();

            float ps[2][2] = {{0.f,0.f},{0.f,0.f}};
            float pd[2][2] = {{0.f,0.f},{0.f,0.f}};
#pragma unroll
            for (int mt = 0; mt < 2; mt++)
#pragma unroll
                for (int nt = 0; nt < 8; nt++) {
                    int c = wn + nt * 8 + 2 * tg;
                    float4 v = acc[mt][nt];
                    float a0 = sas[c], a1 = sas[c + 1];
                    float d0 = sad[c], d1 = sad[c + 1];
                    ps[mt][0] += v.x * a0 + v.y * a1;
                    ps[mt][1] += v.z * a0 + v.w * a1;
                    pd[mt][0] += v.x * d0 + v.y * d1;
                    pd[mt][1] += v.z * d0 + v.w * d1;
                }
#pragma unroll
            for (int mt = 0; mt < 2; mt++)
#pragma unroll
                for (int q = 0; q < 2; q++) {
                    ps[mt][q] += __shfl_xor_sync(0xffffffffu, ps[mt][q], 1);
                    ps[mt][q] += __shfl_xor_sync(0xffffffffu, ps[mt][q], 2);
                    pd[mt][q] += __shfl_xor_sync(0xffffffffu, pd[mt][q], 1);
                    pd[mt][q] += __shfl_xor_sync(0xffffffffu, pd[mt][q], 2);
                }
            const int wc = wid >> 2;
            if (tg == 0) {
#pragma unroll
                for (int mt = 0; mt < 2; mt++) {
                    int r = wm + mt * 16 + g;
                    sE[wc * 128 + r]     = ps[mt][0];
                    sE[wc * 128 + r + 8] = ps[mt][1];
                    sD[wc * 128 + r]     = pd[mt][0];
                    sD[wc * 128 + r + 8] = pd[mt][1];
                }
            }
            __syncthreads();
            if (tid < 128) {
                g_es[(size_t)(m0 + tid) * NH + hn] = sE[tid] + sE[128 + tid];
                g_ed[(size_t)(m0 + tid) * NH + hn] = sD[tid] + sD[128 + tid];
            }
        }
    }
}

// =======================================================================
// K1b: R GEMM — 3-term split-bf16.
// =======================================================================
#define PAS2 20
#define PBN2 68
#define AMAT (128 * PAS2)
#define ASTG (2 * AMAT)
#define BMAT (32 * PBN2)
#define BSTG (2 * BMAT)
#define DG_SMEM (3 * (ASTG + BSTG) * 4)   // 113664 bytes

__global__ __launch_bounds__(256, 2) void r_gemm(const float* __restrict__ res_b)
{
    extern __shared__ uint32_t smem_u[];
    const int m0 = blockIdx.y * 128, n0 = blockIdx.x * 128;
    const int tid = threadIdx.x;
    const int wid = tid >> 5, lane = tid & 31;
    const int wm = (wid & 3) * 32, wn = (wid >> 2) * 64;
    const int g = lane >> 2, tg = lane & 3;

    uint32_t sbase = (uint32_t)__cvta_generic_to_shared(smem_u);
    const uint32_t aB = sbase;
    const uint32_t bB = sbase + 3 * ASTG * 4;

    float4 acc[2][8];
#pragma unroll
    for (int mt = 0; mt < 2; mt++)
#pragma unroll
        for (int nt = 0; nt < 8; nt++) acc[mt][nt] = make_float4(0.f,0.f,0.f,0.f);

    auto issue = [&](int slot, int k0) {
#pragma unroll
        for (int i = 0; i < 2; i++) {
            int c = tid + i * 256;
            int r = c >> 2, seg = c & 3;
            size_t si = (size_t)(m0 + r) * INF + k0 + seg * 8;
            uint32_t d = aB + (slot * ASTG + r * PAS2 + seg * 4) * 4;
            CP16(d, g_Hh + si);
            CP16(d + AMAT * 4, g_Hl + si);
        }
#pragma unroll
        for (int i = 0; i < 2; i++) {
            int c = tid + i * 256;
            int kr = c >> 4, sg = c & 15;
            size_t si = (size_t)(k0 + kr) * FEAT + n0 + sg * 8;
            uint32_t d = bB + (slot * BSTG + kr * PBN2 + sg * 4) * 4;
            CP16(d, g_B1h + si);
            CP16(d + BMAT * 4, g_B1l + si);
        }
        CP_COMMIT();
    };

    auto compute = [&](int slot) {
        const uint32_t aw = aB + slot * ASTG * 4;
        const uint32_t bw = bB + slot * BSTG * 4;
        const int mtx = lane >> 3, mr = lane & 7;
#pragma unroll
        for (int kk2 = 0; kk2 < 2; kk2++) {
            uint32_t ah[2][4], al[2][4];
#pragma unroll
            for (int mt = 0; mt < 2; mt++) {
                int row = wm + mt * 16 + (mtx & 1) * 8 + mr;
                int colw = kk2 * 8 + (mtx >> 1) * 4;
                LDSM_X4(ah[mt], aw + (row * PAS2 + colw) * 4);
                LDSM_X4(al[mt], aw + (AMAT + row * PAS2 + colw) * 4);
            }
#pragma unroll
            for (int p = 0; p < 4; p++) {
                uint32_t bh[4], bl[4];
                int kr = kk2 * 16 + (mtx & 1) * 8 + mr;
                int nb = wn + p * 16 + (mtx >> 1) * 8;
                LDSM_X4T(bh, bw + (kr * PBN2 + (nb >> 1)) * 4);
                LDSM_X4T(bl, bw + (BMAT + kr * PBN2 + (nb >> 1)) * 4);
#pragma unroll
                for (int mt = 0; mt < 2; mt++) {
                    mma_bf16(acc[mt][2*p],   ah[mt], bh[0], bh[1]);
                    mma_bf16(acc[mt][2*p],   ah[mt], bl[0], bl[1]);
                    mma_bf16(acc[mt][2*p],   al[mt], bh[0], bh[1]);
                    mma_bf16(acc[mt][2*p+1], ah[mt], bh[2], bh[3]);
                    mma_bf16(acc[mt][2*p+1], ah[mt], bl[2], bl[3]);
                    mma_bf16(acc[mt][2*p+1], al[mt], bh[2], bh[3]);
                }
            }
        }
    };

    const int NIT = INF / 32;
    issue(0, 0);
    issue(1, 32);
    for (int it = 0; it < NIT; it++) {
        if (it + 2 < NIT) { CP_WAIT(1); } else { CP_WAIT(0); }
        __syncthreads();
        if (it + 2 < NIT) issue((it + 2) % 3, (it + 2) * 32);
        compute(it % 3);
    }

#pragma unroll
    for (int mt = 0; mt < 2; mt++) {
        int r0 = m0 + wm + mt * 16 + g;
#pragma unroll
        for (int nt = 0; nt < 8; nt++) {
            int cc = n0 + wn + nt * 8 + 2 * tg;
            float4 v = acc[mt][nt];
            float bv0 = res_b[cc], bv1 = res_b[cc + 1];
            float2 p0 = make_float2(v.x + bv0, v.y + bv1);
            float2 p1 = make_float2(v.z + bv0, v.w + bv1);
            *reinterpret_cast<float2*>(g_R + (size_t)r0 * FEAT + cc)       = p0;
            *reinterpret_cast<float2*>(g_R + (size_t)(r0 + 8) * FEAT + cc) = p1;
        }
    }
}

// ------------------------------------- K3: softmax (exact R8: proven 107us)
__global__ __launch_bounds__(256) void softmax_kernel(
    const float* __restrict__ Amat, float* __restrict__ alpha_out)
{
    __shared__ float s_es[8];
    __shared__ float s_stat[8];
    __shared__ float red[8][8];
    __shared__ float s_redsum[8];
    __shared__ float s_inv;

    const int bi = blockIdx.x;
    const int b = bi >> 10, i = bi & 1023;
    const int t = threadIdx.x, wid = t >> 5, lane = t & 31;

    const float* arow = Amat + (size_t)bi * Cc;
    float av[4], psum = 0.f;
#pragma unroll
    for (int jj = 0; jj < 4; jj++) {
        int j = t + jj * 256;
        av[jj] = arow[j];
        psum += av[jj];
    }
#pragma unroll
    for (int o = 16; o; o >>= 1) psum += __shfl_xor_sync(0xffffffffu, psum, o);
    if (!lane) s_redsum[wid] = psum;
    if (t < 8) s_es[t] = g_es[(size_t)bi * NH + t];
    __syncthreads();
    if (t == 0) {
        float s = 0.f;
#pragma unroll
        for (int w = 0; w < 8; w++) s += s_redsum[w];
        s_inv = 1.0f / (s + 1e-8f);
    }
    __syncthreads();

    const float inv = s_inv;
    float es[8];
#pragma unroll
    for (int h = 0; h < 8; h++) es[h] = s_es[h];

    const float CT  = 0.96179669f;      // (1/1.5)*log2(e)
    const float CT5 = 0.19235934f;      // 0.2 * CT
    float vv[4][8];
    float lsum[8];
#pragma unroll
    for (int h = 0; h < 8; h++) lsum[h] = 0.f;

#pragma unroll
    for (int jj = 0; jj < 4; jj++) {
        int j = t + jj * 256;
        const float4* edp = reinterpret_cast<const float4*>(g_ed + ((size_t)b * Cc + j) * NH);
        float4 e0 = edp[0], e1 = edp[1];
        float ed[8] = {e0.x,e0.y,e0.z,e0.w,e1.x,e1.y,e1.z,e1.w};
        float aval = av[jj];
        bool mk = (aval > 0.f) || (j == i);
        float base = fmaf(aval * inv, CT, mk ? 0.f : -9.6179667e8f);
#pragma unroll
        for (int h = 0; h < 8; h++) {
            float s = es[h] + ed[h];
            float c = s > 0.f ? CT : CT5;
            float v = fmaf(s, c, base);
            float ev;
            asm("ex2.approx.f32 %0, %1;" : "=f"(ev) : "f"(v));
            vv[jj][h] = ev;
            lsum[h] += ev;
        }
    }
#pragma unroll
    for (int h = 0; h < 8; h++)
#pragma unroll
        for (int o = 16; o; o >>= 1)
            lsum[h] += __shfl_xor_sync(0xffffffffu, lsum[h], o);
    if (!lane) {
#pragma unroll
        for (int h = 0; h < 8; h++) red[wid][h] = lsum[h];
    }
    __syncthreads();
    if (t < 8) {
        float s = 0.f;
#pragma unroll
        for (int w = 0; w < 8; w++) s += red[w][t];
        s_stat[t] = 1.0f / s;
    }
    __syncthreads();
    float ish[8];
#pragma unroll
    for (int h = 0; h < 8; h++) ish[h] = s_stat[h];

    float* oa = alpha_out + (size_t)bi * (Cc * NH);
#pragma unroll
    for (int jj = 0; jj < 4; jj++) {
        int j = t + jj * 256;
#pragma unroll
        for (int h = 0; h < 8; h++) vv[jj][h] *= ish[h];
        float4 o0 = make_float4(vv[jj][0], vv[jj][1], vv[jj][2], vv[jj][3]);
        float4 o1 = make_float4(vv[jj][4], vv[jj][5], vv[jj][6], vv[jj][7]);
        *reinterpret_cast<float4*>(oa + (size_t)j * NH)     = o0;
        *reinterpret_cast<float4*>(oa + (size_t)j * NH + 4) = o1;
    }
#pragma unroll
    for (int h = 0; h < 8; h++) {
        __nv_bfloat16* ot = g_alphaTb + (((size_t)(b * NH + h)) * Cc + i) * Cc;
#pragma unroll
        for (int jj = 0; jj < 4; jj++) {
            int j = t + jj * 256;
            ot[j] = __float2bfloat16(vv[jj][h]);
        }
    }
}

// =======================================================================
// K4: aggr GEMM. per (b,h): Hout[1024,128] = alphaT@Whb + R.
// 128x128 tile, BK=32, 4-stage cp.async + ldmatrix; 2 m-tiles per CTA.
// =======================================================================
#define PAS 20
#define PBS 68
#define A_STG (128 * PAS)
#define B_STG (32 * PBS)
#define NSTAGE 4
#define AGGR_SMEM (NSTAGE * (A_STG + B_STG) * 4)   // 75776 bytes

__global__ __launch_bounds__(256, 2) void aggr_bf16()
{
    extern __shared__ uint32_t smem_u[];
    const int z = blockIdx.z;
    const int b = z >> 3, h = z & 7;
    const __nv_bfloat16* __restrict__ A  = g_alphaTb + (size_t)z * Cc * Cc;
    const __nv_bfloat16* __restrict__ Bp = g_Whb + (size_t)b * Cc * FEAT + h * OF;
    const float* __restrict__ R = g_R    + (size_t)b * Cc * FEAT + h * OF;
    float*       __restrict__ C = g_Hout + (size_t)b * Cc * FEAT + h * OF;

    const int tid = threadIdx.x;
    const int wid = tid >> 5, lane = tid & 31;
    const int wm = (wid & 3) * 32, wn = (wid >> 2) * 64;
    const int g = lane >> 2, tg = lane & 3;

    uint32_t sbase = (uint32_t)__cvta_generic_to_shared(smem_u);
    const uint32_t aBase = sbase;
    const uint32_t bBase = sbase + NSTAGE * A_STG * 4;

    for (int half = 0; half < 2; half++) {
        const int m0 = blockIdx.y * 128 + half * 512;
        if (half) __syncthreads();

        float4 acc[2][8];
#pragma unroll
        for (int mt = 0; mt < 2; mt++)
#pragma unroll
            for (int nt = 0; nt < 8; nt++) acc[mt][nt] = make_float4(0.f,0.f,0.f,0.f);

        auto issue = [&](int slot, int k0) {
#pragma unroll
            for (int i = 0; i < 2; i++) {
                int c = tid + i * 256;
                int r = c >> 2, seg = c & 3;
                const __nv_bfloat16* src = A + (size_t)(m0 + r) * Cc + k0 + seg * 8;
                uint32_t dst = aBase + (slot * A_STG + r * PAS + seg * 4) * 4;
                CP16(dst, src);
            }
#pragma unroll
            for (int i = 0; i < 2; i++) {
                int c = tid + i * 256;
                int kr = c >> 4, seg = c & 15;
                const __nv_bfloat16* src = Bp + (size_t)(k0 + kr) * FEAT + seg * 8;
                uint32_t dst = bBase + (slot * B_STG + kr * PBS + seg * 4) * 4;
                CP16(dst, src);
            }
            CP_COMMIT();
        };

        auto compute = [&](int slot) {
            const uint32_t aw = aBase + slot * A_STG * 4;
            const uint32_t bw = bBase + slot * B_STG * 4;
            const int mtx = lane >> 3;
            const int mr  = lane & 7;
#pragma unroll
            for (int kk2 = 0; kk2 < 2; kk2++) {
                uint32_t af[2][4];
#pragma unroll
                for (int mt = 0; mt < 2; mt++) {
                    int row = wm + mt * 16 + (mtx & 1) * 8 + mr;
                    int col = kk2 * 8 + (mtx >> 1) * 4;
                    LDSM_X4(af[mt], aw + (row * PAS + col) * 4);
                }
#pragma unroll
                for (int p = 0; p < 4; p++) {
                    uint32_t bf[4];
                    int kr = kk2 * 16 + (mtx & 1) * 8 + mr;
                    int nb = wn + p * 16 + (mtx >> 1) * 8;
                    LDSM_X4T(bf, bw + (kr * PBS + (nb >> 1)) * 4);
#pragma unroll
                    for (int mt = 0; mt < 2; mt++) {
                        mma_bf16(acc[mt][2 * p],     af[mt], bf[0], bf[1]);
                        mma_bf16(acc[mt][2 * p + 1], af[mt], bf[2], bf[3]);
                    }
                }
            }
        };

        const int NIT = Cc / 32;
        issue(0, 0);
        issue(1, 32);
        issue(2, 64);
        for (int it = 0; it < NIT; it++) {
            if (it + 3 < NIT)      { CP_WAIT(2); }
            else if (it + 2 < NIT) { CP_WAIT(1); }
            else                   { CP_WAIT(0); }
            __syncthreads();
            if (it + 3 < NIT) issue((it + 3) % NSTAGE, (it + 3) * 32);
            compute(it % NSTAGE);
        }

#pragma unroll
        for (int mt = 0; mt < 2; mt++) {
            int r0 = m0 + wm + mt * 16 + g;
#pragma unroll
            for (int nt = 0; nt < 8; nt++) {
                int cc = wn + nt * 8 + 2 * tg;
                float4 v = acc[mt][nt];
                float2 ra  = *reinterpret_cast<const float2*>(R + (size_t)r0 * FEAT + cc);
                float2 rbv = *reinterpret_cast<const float2*>(R + (size_t)(r0 + 8) * FEAT + cc);
                float2 p0 = make_float2(v.x + ra.x,  v.y + ra.y);
                float2 p1 = make_float2(v.z + rbv.x, v.w + rbv.y);
                *reinterpret_cast<float2*>(C + (size_t)r0 * FEAT + cc)       = p0;
                *reinterpret_cast<float2*>(C + (size_t)(r0 + 8) * FEAT + cc) = p1;
            }
        }
    }
}

// ------------------------------------------------- K5: LayerNorm + ReLU ----
__global__ __launch_bounds__(256) void ln_kernel(
    const float* __restrict__ gamma, const float* __restrict__ beta,
    float* __restrict__ out)
{
    __shared__ float rs[8], rs2[8];
    __shared__ float s_mu, s_rstd;
    const int bi = blockIdx.x;
    const int t = threadIdx.x, wid = t >> 5, lane = t & 31;
    const float* x = g_Hout + (size_t)bi * FEAT;
    float xs[4], s = 0.f, s2 = 0.f;
#pragma unroll
    for (int jj = 0; jj < 4; jj++) {
        float v = x[t + jj * 256];
        xs[jj] = v; s += v; s2 += v * v;
    }
#pragma unroll
    for (int o = 16; o; o >>= 1) {
        s  += __shfl_xor_sync(0xffffffffu, s, o);
        s2 += __shfl_xor_sync(0xffffffffu, s2, o);
    }
    if (!lane) { rs[wid] = s; rs2[wid] = s2; }
    __syncthreads();
    if (t == 0) {
        float ts = 0.f, ts2 = 0.f;
#pragma unroll
        for (int w = 0; w < 8; w++) { ts += rs[w]; ts2 += rs2[w]; }
        float mu = ts * (1.0f / FEAT);
        float var = ts2 * (1.0f / FEAT) - mu * mu;
        s_mu = mu;
        s_rstd = rsqrtf(var + 1e-5f);
    }
    __syncthreads();
    const float mu = s_mu, rstd = s_rstd;
#pragma unroll
    for (int jj = 0; jj < 4; jj++) {
        int f = t + jj * 256;
        float y = (xs[jj] - mu) * rstd * gamma[f] + beta[f];
        out[(size_t)bi * FEAT + f] = fmaxf(y, 0.f);
    }
}

// --------------------------------------------------------------------------
extern "C" void kernel_launch(void* const* d_in, const int* in_sizes, int n_in,
                              void* d_out, int out_size)
{
    const float* H      = (const float*)d_in[0];
    const float* Amat   = (const float*)d_in[1];
    const float* W      = (const float*)d_in[2];
    const float* a_attn = (const float*)d_in[3];
    const float* res_W  = (const float*)d_in[4];
    const float* res_b  = (const float*)d_in[5];
    const float* gamma  = (const float*)d_in[6];
    const float* beta   = (const float*)d_in[7];
    float* out = (float*)d_out;

    static cudaStream_t s2 = nullptr;
    static cudaEvent_t evP, evR;
    static bool inited = false;
    if (!inited) {
        cudaFuncSetAttribute(wh_gemm,
            cudaFuncAttributeMaxDynamicSharedMemorySize, WH_SMEM);
        cudaFuncSetAttribute(r_gemm,
            cudaFuncAttributeMaxDynamicSharedMemorySize, DG_SMEM);
        cudaFuncSetAttribute(aggr_bf16,
            cudaFuncAttributeMaxDynamicSharedMemorySize, AGGR_SMEM);
        cudaStreamCreateWithFlags(&s2, cudaStreamNonBlocking);
        cudaEventCreateWithFlags(&evP, cudaEventDisableTiming);
        cudaEventCreateWithFlags(&evR, cudaEventDisableTiming);
        inited = true;
    }

    // K0: prep (main)
    const int prep_tot = (H_ELE + 2 * W_ELE) / 4;
    prep_kernel<<<(prep_tot + 255) / 256, 256>>>(H, W, res_W);
    cudaEventRecord(evP, 0);

    // K1a: Wh gemm (tf32, one-wave) + fused scores (main)
    dim3 g1(FEAT / 128, ROWS / 256, 1);   // 8 x 32 = 256 CTAs
    wh_gemm<<<g1, 256, WH_SMEM>>>(a_attn);

    // K1b: R gemm on s2 — overlaps softmax; aggr waits on it (R14-proven)
    dim3 gr(FEAT / 128, ROWS / 128, 1);   // 8 x 64
    cudaStreamWaitEvent(s2, evP, 0);
    r_gemm<<<gr, 256, DG_SMEM, s2>>>(res_b);
    cudaEventRecord(evR, s2);

    // K3: softmax (main, full grid)
    softmax_kernel<<<ROWS, 256>>>(Amat, out + X_ELEMS);

    // K4: aggr (main) — needs alphaT (softmax) and g_R (r_gemm)
    cudaStreamWaitEvent(0, evR, 0);
    dim3 g4(1, Cc / 256, Bb * NH);
    aggr_bf16<<<g4, 256, AGGR_SMEM>>>();

    // K5: LayerNorm + ReLU
    ln_kernel<<<ROWS, 256>>>(gamma, beta, out);
}